// round 9
// baseline (speedup 1.0000x reference)
#include <cuda_runtime.h>
#include <cstdint>

#define L_SEQ 512
#define NB    64
#define HID   1024
#define EMB   512
#define NC    4096   // 4 gates * HID, interleaved col = j*4 + g  (g: 0=i,1=f,2=c,3=o)
#define NCTAS 128    // persistent grid; 1 CTA/SM -> all resident

typedef unsigned long long ull;

// ---------------- device scratch (no allocs allowed) ----------------
__device__ float g_xproj[(size_t)L_SEQ * NB * NC];     // 512 MB: bias + x-part preacts
__device__ float g_Wr[(size_t)(HID + EMB) * NC];       // 25 MB: interleaved weights
__device__ float g_br[NC];                             // interleaved bias
__device__ float g_h[2 * HID * NB];                    // ping-pong, layout [j][m]
__device__ volatile unsigned g_bar;                    // grid barrier arrival counter

// ---------------- packed fp32x2 helpers (FFMA2 on sm_103a) ----------------
__device__ __forceinline__ ull pk2(float a, float b) {
    ull r; asm("mov.b64 %0, {%1, %2};" : "=l"(r) : "f"(a), "f"(b)); return r;
}
__device__ __forceinline__ ull dup2(float v) {
    ull r; asm("mov.b64 %0, {%1, %1};" : "=l"(r) : "f"(v)); return r;
}
__device__ __forceinline__ void up2(ull v, float& lo, float& hi) {
    asm("mov.b64 {%0, %1}, %2;" : "=f"(lo), "=f"(hi) : "l"(v));
}
__device__ __forceinline__ void fma2(ull& d, ull a, ull b) {
    asm("fma.rn.f32x2 %0, %1, %2, %0;" : "+l"(d) : "l"(a), "l"(b));
}
__device__ __forceinline__ ull add2(ull a, ull b) {
    ull r; asm("add.rn.f32x2 %0, %1, %2;" : "=l"(r) : "l"(a), "l"(b)); return r;
}
__device__ __forceinline__ uint32_t su32(const void* p) {
    return (uint32_t)__cvta_generic_to_shared(p);
}
__device__ __forceinline__ void cpa16(uint32_t d, const float* g) {
    asm volatile("cp.async.cg.shared.global [%0], [%1], 16;" :: "r"(d), "l"(g));
}
#define CP_COMMIT() asm volatile("cp.async.commit_group;" ::: "memory")
#define CP_WAIT0()  asm volatile("cp.async.wait_group 0;" ::: "memory")
#define CP_WAIT1()  asm volatile("cp.async.wait_group 1;" ::: "memory")

// partial-region bank swizzle (col 0..31, P 0..31)
__device__ __forceinline__ int swz(int c, int P) {
    return (c & 16) | ((c ^ P) & 15);
}

// ---------------- init: zero h0 (ping 0) + barrier counter ----------------
__global__ void k_init() {
    int i = blockIdx.x * blockDim.x + threadIdx.x;
    if (i < HID * NB) g_h[i] = 0.f;
    if (i == 0) g_bar = 0;
}

// ---------------- weight/bias reorg: col = j*4 + g ----------------
__global__ void k_reorg(const float* __restrict__ Wi, const float* __restrict__ bi,
                        const float* __restrict__ Wf, const float* __restrict__ bf,
                        const float* __restrict__ Wc, const float* __restrict__ bc,
                        const float* __restrict__ Wo, const float* __restrict__ bo) {
    int idx = blockIdx.x * 256 + threadIdx.x;
    if (idx < (HID + EMB) * HID) {
        int k = idx >> 10, j = idx & (HID - 1);
        size_t s = (size_t)k * HID + j;
        float4 v = make_float4(Wi[s], Wf[s], Wc[s], Wo[s]);
        *(float4*)&g_Wr[(size_t)k * NC + j * 4] = v;
    }
    if (idx < HID) {
        *(float4*)&g_br[idx * 4] = make_float4(bi[idx], bf[idx], bc[idx], bo[idx]);
    }
}

// ---------------- kernel 1: embedding gather + input projection ----------------
#define BPAD 20
__global__ __launch_bounds__(256) void k_embed_proj(
    const int* __restrict__ x, const float* __restrict__ emb)
{
    __shared__ float a2[16][132];
    __shared__ float bsh[16 * 16 * BPAD];

    int tid = threadIdx.x;
    int jb  = blockIdx.x * 256;
    int by  = blockIdx.y;

    int arow  = tid & 63;
    int ahalf = tid >> 6;
    long tok  = x[by * 64 + arow];
    const float* erow = emb + (size_t)tok * EMB + ahalf * 4;

    int mg = tid >> 4;
    int cg = tid & 15;

    ull acc[32];
    {
        float4 b0 = *(const float4*)(g_br + jb + cg * 16);
        float4 b1 = *(const float4*)(g_br + jb + cg * 16 + 4);
        float4 b2 = *(const float4*)(g_br + jb + cg * 16 + 8);
        float4 b3 = *(const float4*)(g_br + jb + cg * 16 + 12);
        ull p[8] = { pk2(b0.x, b0.y), pk2(b0.z, b0.w), pk2(b1.x, b1.y), pk2(b1.z, b1.w),
                     pk2(b2.x, b2.y), pk2(b2.z, b2.w), pk2(b3.x, b3.y), pk2(b3.z, b3.w) };
#pragma unroll
        for (int m = 0; m < 4; m++)
#pragma unroll
            for (int q = 0; q < 8; q++) acc[m * 8 + q] = p[q];
    }

    float4 va;
    float4 rb[4];
#define E_LOAD(KB)                                                               \
    va = *(const float4*)(erow + (KB));                                         \
    _Pragma("unroll")                                                            \
    for (int i_ = 0; i_ < 4; i_++) {                                             \
        int f_ = tid + i_ * 256; int r_ = f_ >> 6, q_ = f_ & 63;                 \
        rb[i_] = *(const float4*)&g_Wr[(size_t)(HID + (KB) + r_) * NC + jb + q_ * 4]; \
    }

    E_LOAD(0)

    for (int kb = 0; kb < EMB; kb += 16) {
        __syncthreads();
        {
            int k0 = ahalf * 4;
            *(float2*)&a2[k0 + 0][2 * arow] = make_float2(va.x, va.x);
            *(float2*)&a2[k0 + 1][2 * arow] = make_float2(va.y, va.y);
            *(float2*)&a2[k0 + 2][2 * arow] = make_float2(va.z, va.z);
            *(float2*)&a2[k0 + 3][2 * arow] = make_float2(va.w, va.w);
        }
#pragma unroll
        for (int i_ = 0; i_ < 4; i_++) {
            int f_ = tid + i_ * 256; int r_ = f_ >> 6, q_ = f_ & 63;
            *(float4*)&bsh[r_ * (16 * BPAD) + (q_ >> 2) * BPAD + (q_ & 3) * 4] = rb[i_];
        }
        __syncthreads();
        if (kb + 16 < EMB) { E_LOAD(kb + 16) }

        const float* bp = &bsh[cg * BPAD];
#pragma unroll
        for (int k = 0; k < 16; k++) {
            ulonglong2 aa0 = *(const ulonglong2*)&a2[k][8 * mg];
            ulonglong2 aa1 = *(const ulonglong2*)&a2[k][8 * mg + 4];
            ulonglong2 bb0 = *(const ulonglong2*)(bp + k * (16 * BPAD));
            ulonglong2 bb1 = *(const ulonglong2*)(bp + k * (16 * BPAD) + 4);
            ulonglong2 bb2 = *(const ulonglong2*)(bp + k * (16 * BPAD) + 8);
            ulonglong2 bb3 = *(const ulonglong2*)(bp + k * (16 * BPAD) + 12);
            ull am[4] = { aa0.x, aa0.y, aa1.x, aa1.y };
            ull bq[8] = { bb0.x, bb0.y, bb1.x, bb1.y, bb2.x, bb2.y, bb3.x, bb3.y };
#pragma unroll
            for (int m = 0; m < 4; m++)
#pragma unroll
                for (int q = 0; q < 8; q++) fma2(acc[m * 8 + q], am[m], bq[q]);
        }
    }
#undef E_LOAD

#pragma unroll
    for (int m = 0; m < 4; m++) {
        float* op = g_xproj + (size_t)(by * 64 + mg * 4 + m) * NC + jb + cg * 16;
        float l0, h0, l1, h1;
#pragma unroll
        for (int q = 0; q < 4; q++) {
            up2(acc[m * 8 + 2 * q], l0, h0);
            up2(acc[m * 8 + 2 * q + 1], l1, h1);
            *(float4*)(op + q * 4) = make_float4(l0, h0, l1, h1);
        }
    }
}

// ---------------- kernel 2: PERSISTENT LSTM (all 512 steps, one launch) ---------
// 128 CTAs x 512 threads, 1 CTA/SM. Per CTA: 8 hidden units (32 interleaved cols),
// W slice 1024x32 = 128 KB persistent smem. 16 warps = 16-way per-warp split-K
// (64 k each), private cp.async double buffers (no block barrier in mainloop).
// Thread tile: 4 m-pairs x 8 cols = 32 packed accs; per k: 4 LDS.128 + 32 FFMA2.
#define W_FLOATS  32768                   // 1024 x 32
#define STG_FLOATS 16384                  // 16 warps x 2 stages x (8 rows x 64 m)
#define SMEM_LSTM ((W_FLOATS + STG_FLOATS) * 4)   // 192 KB

__global__ __launch_bounds__(512) void k_lstm(float* __restrict__ out)
{
    extern __shared__ __align__(16) float sm[];
    float* Wsm = sm;                  // [k 0..1023][32 cols]
    float* stg = sm + W_FLOATS;       // per-warp stages; partials alias after loop

    int tid = threadIdx.x;
    int jb8 = blockIdx.x * 8;         // hidden units jb8..jb8+7
    int C0  = jb8 * 4;                // interleaved col base (32 cols)

    // ---- load persistent W slice (coalesced: 8192 float4 / 512 threads) ----
#pragma unroll
    for (int i = 0; i < 16; i++) {
        int f = tid + i * 512;        // float4 index 0..8191
        int r = f >> 3, q = f & 7;
        *(float4*)&Wsm[r * 32 + q * 4] =
            *(const float4*)&g_Wr[(size_t)r * NC + C0 + q * 4];
    }

    int lane = tid & 31, wid = tid >> 5;   // wid 0..15 = split-K slice (64 k each)
    int mi = lane >> 2;               // 0..7 -> m-pairs mi*4..+3
    int ci = lane & 3;                // 0..3 -> cols ci*8..+7
    float* stW = stg + wid * 1024;    // 2 stages x 512 floats

    // gate-phase mapping (step-invariant)
    int m  = tid & 63;                // batch row
    int jq = tid >> 6;                // 0..7 -> hidden unit jb8+jq
    int P  = m >> 1, e = m & 1;
    int j  = jb8 + jq;
    float c_reg = 0.f;

    __syncthreads();

#define PFW(DST, SUBBASE) do {                                                   \
    _Pragma("unroll")                                                            \
    for (int j_ = 0; j_ < 4; j_++) {                                             \
        int idx_ = lane + j_ * 32; int r_ = idx_ >> 4, p_ = idx_ & 15;           \
        cpa16(su32((DST) + r_ * 64 + p_ * 4),                                    \
              hp + (size_t)((SUBBASE) + r_) * 64 + p_ * 4);                      \
    }                                                                            \
    CP_COMMIT();                                                                 \
} while (0)

    for (int t = 0; t < L_SEQ; t++) {
        const float* hprev = g_h + (size_t)(t & 1) * (HID * NB);
        float*       hnext = g_h + (size_t)((t + 1) & 1) * (HID * NB);
        const float* hp = hprev + (size_t)(wid * 64) * 64;   // this warp's k-rows

        // x-part preacts (independent of h; issued early)
        float4 xp = *(const float4*)&g_xproj[((size_t)t * 64 + m) * NC + C0 + jq * 4];

        ull acc[32];
#pragma unroll
        for (int i = 0; i < 32; i++) acc[i] = 0;

        PFW(stW, 0);
        PFW(stW + 512, 8);

        for (int sub = 0; sub < 8; sub++) {
            if (sub == 7) { CP_WAIT0(); } else { CP_WAIT1(); }
            __syncwarp();
            const float* cur = stW + ((sub & 1) << 9);
            const float* wp  = Wsm + (wid * 64 + sub * 8) * 32 + ci * 8;
#pragma unroll
            for (int kk = 0; kk < 8; kk++) {
                ulonglong2 a0 = *(const ulonglong2*)(cur + kk * 64 + mi * 8);
                ulonglong2 a1 = *(const ulonglong2*)(cur + kk * 64 + mi * 8 + 4);
                float4 b0 = *(const float4*)(wp + kk * 32);
                float4 b1 = *(const float4*)(wp + kk * 32 + 4);
                ull d0 = dup2(b0.x), d1 = dup2(b0.y), d2 = dup2(b0.z), d3 = dup2(b0.w);
                ull d4 = dup2(b1.x), d5 = dup2(b1.y), d6 = dup2(b1.z), d7 = dup2(b1.w);
                fma2(acc[0],  a0.x, d0); fma2(acc[1],  a0.x, d1);
                fma2(acc[2],  a0.x, d2); fma2(acc[3],  a0.x, d3);
                fma2(acc[4],  a0.x, d4); fma2(acc[5],  a0.x, d5);
                fma2(acc[6],  a0.x, d6); fma2(acc[7],  a0.x, d7);
                fma2(acc[8],  a0.y, d0); fma2(acc[9],  a0.y, d1);
                fma2(acc[10], a0.y, d2); fma2(acc[11], a0.y, d3);
                fma2(acc[12], a0.y, d4); fma2(acc[13], a0.y, d5);
                fma2(acc[14], a0.y, d6); fma2(acc[15], a0.y, d7);
                fma2(acc[16], a1.x, d0); fma2(acc[17], a1.x, d1);
                fma2(acc[18], a1.x, d2); fma2(acc[19], a1.x, d3);
                fma2(acc[20], a1.x, d4); fma2(acc[21], a1.x, d5);
                fma2(acc[22], a1.x, d6); fma2(acc[23], a1.x, d7);
                fma2(acc[24], a1.y, d0); fma2(acc[25], a1.y, d1);
                fma2(acc[26], a1.y, d2); fma2(acc[27], a1.y, d3);
                fma2(acc[28], a1.y, d4); fma2(acc[29], a1.y, d5);
                fma2(acc[30], a1.y, d6); fma2(acc[31], a1.y, d7);
            }
            if (sub < 6) { PFW(stW + ((sub & 1) << 9), (sub + 2) * 8); }
        }

        // ---- split-K reduce 16 -> 8 via smem (alias stage region: 8192 ull) ----
        __syncthreads();
        ull* R = (ull*)stg;
        if (wid >= 8) {
            int base = (wid - 8) * 1024;
#pragma unroll
            for (int p = 0; p < 4; p++) {
                int Pp = mi * 4 + p;
#pragma unroll
                for (int cc = 0; cc < 8; cc++) {
                    int c = ci * 8 + cc;
                    R[base + Pp * 32 + swz(c, Pp)] = acc[p * 8 + cc];
                }
            }
        }
        __syncthreads();
        if (wid < 8) {
            int base = wid * 1024;
#pragma unroll
            for (int p = 0; p < 4; p++) {
                int Pp = mi * 4 + p;
#pragma unroll
                for (int cc = 0; cc < 8; cc++) {
                    int c = ci * 8 + cc;
                    int a = base + Pp * 32 + swz(c, Pp);
                    R[a] = add2(R[a], acc[p * 8 + cc]);
                }
            }
        }
        __syncthreads();

        // ---- gates: thread -> (m, j) ----
        float pre[4];
#pragma unroll
        for (int g = 0; g < 4; g++) {
            int c = jq * 4 + g;
            int o = P * 32 + swz(c, P);
            ull s = add2(add2(add2(R[o], R[1024 + o]),
                              add2(R[2048 + o], R[3072 + o])),
                         add2(add2(R[4096 + o], R[5120 + o]),
                              add2(R[6144 + o], R[7168 + o])));
            float lo, hi; up2(s, lo, hi);
            pre[g] = e ? hi : lo;
        }
        pre[0] += xp.x; pre[1] += xp.y; pre[2] += xp.z; pre[3] += xp.w;

        float is = 1.f / (1.f + __expf(-pre[0]));
        float fs = 1.f / (1.f + __expf(-pre[1]));
        float gt = tanhf(pre[2]);
        float os = 1.f / (1.f + __expf(-pre[3]));

        float cn = fs * c_reg + is * gt;
        c_reg = cn;
        float hv = os * tanhf(cn);
        hnext[(size_t)j * 64 + m] = hv;                   // coalesced (m across lanes)
        out[((size_t)t * 64 + m) * 1024 + j] = hv;

        // ---- software grid barrier (all 128 CTAs resident: 1 CTA/SM) ----
        __threadfence();
        __syncthreads();
        if (tid == 0) {
            atomicAdd((unsigned*)&g_bar, 1u);
            unsigned target = (unsigned)(t + 1) * NCTAS;
            while (g_bar < target) { }
        }
        __syncthreads();
        __threadfence();
    }
#undef PFW
}

// ---------------- launcher ----------------
extern "C" void kernel_launch(void* const* d_in, const int* in_sizes, int n_in,
                              void* d_out, int out_size)
{
    const int*   x   = (const int*)  d_in[0];
    const float* emb = (const float*)d_in[1];
    const float* Wi  = (const float*)d_in[2];
    const float* bi  = (const float*)d_in[3];
    const float* Wf  = (const float*)d_in[4];
    const float* bf  = (const float*)d_in[5];
    const float* Wc  = (const float*)d_in[6];
    const float* bc  = (const float*)d_in[7];
    const float* Wo  = (const float*)d_in[8];
    const float* bo  = (const float*)d_in[9];
    float* out = (float*)d_out;
    (void)in_sizes; (void)n_in; (void)out_size;

    static bool attr_done = false;
    if (!attr_done) {
        cudaFuncSetAttribute(k_lstm, cudaFuncAttributeMaxDynamicSharedMemorySize,
                             SMEM_LSTM);
        attr_done = true;
    }

    k_init<<<(HID * NB + 255) / 256, 256>>>();
    k_reorg<<<((HID + EMB) * HID + 255) / 256, 256>>>(Wi, bi, Wf, bf, Wc, bc, Wo, bo);

    dim3 g1(16, 512);
    k_embed_proj<<<g1, 256>>>(x, emb);

    k_lstm<<<NCTAS, 512, SMEM_LSTM>>>(out);
}

// round 10
// speedup vs baseline: 1.0970x; 1.0970x over previous
#include <cuda_runtime.h>
#include <cstdint>

#define L_SEQ 512
#define NB    64
#define HID   1024
#define EMB   512
#define NC    4096   // 4 gates * HID, interleaved col = j*4 + g  (g: 0=i,1=f,2=c,3=o)
#define NCTAS 256    // persistent grid; 2 CTAs/SM -> all resident

typedef unsigned long long ull;

// ---------------- device scratch (no allocs allowed) ----------------
__device__ float g_xproj[(size_t)L_SEQ * NB * NC];     // 512 MB: bias + x-part preacts
__device__ float g_Wr[(size_t)(HID + EMB) * NC];       // 25 MB: interleaved weights
__device__ float g_br[NC];                             // interleaved bias
__device__ float g_h[2 * HID * NB];                    // ping-pong, layout [j][m]
__device__ volatile unsigned g_bar;                    // grid barrier arrival counter

// ---------------- packed fp32x2 helpers (FFMA2 on sm_103a) ----------------
__device__ __forceinline__ ull pk2(float a, float b) {
    ull r; asm("mov.b64 %0, {%1, %2};" : "=l"(r) : "f"(a), "f"(b)); return r;
}
__device__ __forceinline__ ull dup2(float v) {
    ull r; asm("mov.b64 %0, {%1, %1};" : "=l"(r) : "f"(v)); return r;
}
__device__ __forceinline__ void up2(ull v, float& lo, float& hi) {
    asm("mov.b64 {%0, %1}, %2;" : "=f"(lo), "=f"(hi) : "l"(v));
}
__device__ __forceinline__ void fma2(ull& d, ull a, ull b) {
    asm("fma.rn.f32x2 %0, %1, %2, %0;" : "+l"(d) : "l"(a), "l"(b));
}
__device__ __forceinline__ ull add2(ull a, ull b) {
    ull r; asm("add.rn.f32x2 %0, %1, %2;" : "=l"(r) : "l"(a), "l"(b)); return r;
}
__device__ __forceinline__ uint32_t su32(const void* p) {
    return (uint32_t)__cvta_generic_to_shared(p);
}
__device__ __forceinline__ void cpa16(uint32_t d, const float* g) {
    asm volatile("cp.async.cg.shared.global [%0], [%1], 16;" :: "r"(d), "l"(g));
}
#define CP_COMMIT() asm volatile("cp.async.commit_group;" ::: "memory")
#define CP_WAIT0()  asm volatile("cp.async.wait_group 0;" ::: "memory")
#define CP_WAIT1()  asm volatile("cp.async.wait_group 1;" ::: "memory")

// partial-region bank swizzle: c in 0..15, P in 0..31
__device__ __forceinline__ int swz(int c, int P) {
    return (c ^ (P >> 2) ^ ((P & 3) << 2)) & 15;
}

// ---------------- init: zero h0 (ping 0) + barrier counter ----------------
__global__ void k_init() {
    int i = blockIdx.x * blockDim.x + threadIdx.x;
    if (i < HID * NB) g_h[i] = 0.f;
    if (i == 0) g_bar = 0;
}

// ---------------- weight/bias reorg: col = j*4 + g ----------------
__global__ void k_reorg(const float* __restrict__ Wi, const float* __restrict__ bi,
                        const float* __restrict__ Wf, const float* __restrict__ bf,
                        const float* __restrict__ Wc, const float* __restrict__ bc,
                        const float* __restrict__ Wo, const float* __restrict__ bo) {
    int idx = blockIdx.x * 256 + threadIdx.x;
    if (idx < (HID + EMB) * HID) {
        int k = idx >> 10, j = idx & (HID - 1);
        size_t s = (size_t)k * HID + j;
        float4 v = make_float4(Wi[s], Wf[s], Wc[s], Wo[s]);
        *(float4*)&g_Wr[(size_t)k * NC + j * 4] = v;
    }
    if (idx < HID) {
        *(float4*)&g_br[idx * 4] = make_float4(bi[idx], bf[idx], bc[idx], bo[idx]);
    }
}

// ---------------- kernel 1: embedding gather + input projection ----------------
#define BPAD 20
__global__ __launch_bounds__(256) void k_embed_proj(
    const int* __restrict__ x, const float* __restrict__ emb)
{
    __shared__ float a2[16][132];
    __shared__ float bsh[16 * 16 * BPAD];

    int tid = threadIdx.x;
    int jb  = blockIdx.x * 256;
    int by  = blockIdx.y;

    int arow  = tid & 63;
    int ahalf = tid >> 6;
    long tok  = x[by * 64 + arow];
    const float* erow = emb + (size_t)tok * EMB + ahalf * 4;

    int mg = tid >> 4;
    int cg = tid & 15;

    ull acc[32];
    {
        float4 b0 = *(const float4*)(g_br + jb + cg * 16);
        float4 b1 = *(const float4*)(g_br + jb + cg * 16 + 4);
        float4 b2 = *(const float4*)(g_br + jb + cg * 16 + 8);
        float4 b3 = *(const float4*)(g_br + jb + cg * 16 + 12);
        ull p[8] = { pk2(b0.x, b0.y), pk2(b0.z, b0.w), pk2(b1.x, b1.y), pk2(b1.z, b1.w),
                     pk2(b2.x, b2.y), pk2(b2.z, b2.w), pk2(b3.x, b3.y), pk2(b3.z, b3.w) };
#pragma unroll
        for (int m = 0; m < 4; m++)
#pragma unroll
            for (int q = 0; q < 8; q++) acc[m * 8 + q] = p[q];
    }

    float4 va;
    float4 rb[4];
#define E_LOAD(KB)                                                               \
    va = *(const float4*)(erow + (KB));                                         \
    _Pragma("unroll")                                                            \
    for (int i_ = 0; i_ < 4; i_++) {                                             \
        int f_ = tid + i_ * 256; int r_ = f_ >> 6, q_ = f_ & 63;                 \
        rb[i_] = *(const float4*)&g_Wr[(size_t)(HID + (KB) + r_) * NC + jb + q_ * 4]; \
    }

    E_LOAD(0)

    for (int kb = 0; kb < EMB; kb += 16) {
        __syncthreads();
        {
            int k0 = ahalf * 4;
            *(float2*)&a2[k0 + 0][2 * arow] = make_float2(va.x, va.x);
            *(float2*)&a2[k0 + 1][2 * arow] = make_float2(va.y, va.y);
            *(float2*)&a2[k0 + 2][2 * arow] = make_float2(va.z, va.z);
            *(float2*)&a2[k0 + 3][2 * arow] = make_float2(va.w, va.w);
        }
#pragma unroll
        for (int i_ = 0; i_ < 4; i_++) {
            int f_ = tid + i_ * 256; int r_ = f_ >> 6, q_ = f_ & 63;
            *(float4*)&bsh[r_ * (16 * BPAD) + (q_ >> 2) * BPAD + (q_ & 3) * 4] = rb[i_];
        }
        __syncthreads();
        if (kb + 16 < EMB) { E_LOAD(kb + 16) }

        const float* bp = &bsh[cg * BPAD];
#pragma unroll
        for (int k = 0; k < 16; k++) {
            ulonglong2 aa0 = *(const ulonglong2*)&a2[k][8 * mg];
            ulonglong2 aa1 = *(const ulonglong2*)&a2[k][8 * mg + 4];
            ulonglong2 bb0 = *(const ulonglong2*)(bp + k * (16 * BPAD));
            ulonglong2 bb1 = *(const ulonglong2*)(bp + k * (16 * BPAD) + 4);
            ulonglong2 bb2 = *(const ulonglong2*)(bp + k * (16 * BPAD) + 8);
            ulonglong2 bb3 = *(const ulonglong2*)(bp + k * (16 * BPAD) + 12);
            ull am[4] = { aa0.x, aa0.y, aa1.x, aa1.y };
            ull bq[8] = { bb0.x, bb0.y, bb1.x, bb1.y, bb2.x, bb2.y, bb3.x, bb3.y };
#pragma unroll
            for (int m = 0; m < 4; m++)
#pragma unroll
                for (int q = 0; q < 8; q++) fma2(acc[m * 8 + q], am[m], bq[q]);
        }
    }
#undef E_LOAD

#pragma unroll
    for (int m = 0; m < 4; m++) {
        float* op = g_xproj + (size_t)(by * 64 + mg * 4 + m) * NC + jb + cg * 16;
        float l0, h0, l1, h1;
#pragma unroll
        for (int q = 0; q < 4; q++) {
            up2(acc[m * 8 + 2 * q], l0, h0);
            up2(acc[m * 8 + 2 * q + 1], l1, h1);
            *(float4*)(op + q * 4) = make_float4(l0, h0, l1, h1);
        }
    }
}

// ---------------- kernel 2: PERSISTENT LSTM (all 512 steps, one launch) ---------
// 256 CTAs x 256 threads, 2 CTAs/SM (all resident). CTA: 4 hidden units (16 cols),
// W slice 1024x16 = 64 KB persistent smem. 8 warps = 8-way per-warp split-K
// (128 k each), private cp.async double buffers (no block barrier in mainloop).
// Thread tile: 4 m-pairs x 4 cols = 16 packed accs; per k: 3 LDS.128 + 16 FFMA2.
#define W_FLOATS   16384                  // 1024 x 16
#define STG_FLOATS 8192                   // 8 warps x 2 stages x (8 rows x 64 m)
#define SMEM_LSTM  ((W_FLOATS + STG_FLOATS) * 4)   // 96 KB

__global__ __launch_bounds__(256, 2) void k_lstm(float* __restrict__ out)
{
    extern __shared__ __align__(16) float sm[];
    float* Wsm = sm;                  // [k 0..1023][16 cols]
    float* stg = sm + W_FLOATS;       // per-warp stages; partials alias after loop

    int tid = threadIdx.x;
    int jb  = blockIdx.x * 4;         // hidden units jb..jb+3
    int C0  = jb * 4;                 // interleaved col base (16 cols)

    // ---- load persistent W slice (coalesced: 4096 float4 / 256 threads) ----
#pragma unroll
    for (int i = 0; i < 16; i++) {
        int f = tid + i * 256;        // float4 index 0..4095
        int r = f >> 2, q = f & 3;
        *(float4*)&Wsm[r * 16 + q * 4] =
            *(const float4*)&g_Wr[(size_t)r * NC + C0 + q * 4];
    }

    int lane = tid & 31, wid = tid >> 5;   // wid 0..7 = split-K slice (128 k each)
    int mi = lane >> 2;               // 0..7 -> m-pairs mi*4..+3
    int ci = lane & 3;                // 0..3 -> cols ci*4..+3
    float* stW = stg + wid * 1024;    // 2 stages x 512 floats

    // gate-phase mapping (step-invariant): m fastest for coalesced h writes
    int m  = tid & 63;                // batch row
    int jl = tid >> 6;                // 0..3 -> hidden unit jb+jl
    int P  = m >> 1, e = m & 1;
    int j  = jb + jl;
    float c_reg = 0.f;

    __syncthreads();

#define PFW(DST, SUBBASE) do {                                                   \
    _Pragma("unroll")                                                            \
    for (int j_ = 0; j_ < 4; j_++) {                                             \
        int idx_ = lane + j_ * 32; int r_ = idx_ >> 4, p_ = idx_ & 15;           \
        cpa16(su32((DST) + r_ * 64 + p_ * 4),                                    \
              hp + (size_t)((SUBBASE) + r_) * 64 + p_ * 4);                      \
    }                                                                            \
    CP_COMMIT();                                                                 \
} while (0)

    for (int t = 0; t < L_SEQ; t++) {
        const float* hprev = g_h + (size_t)(t & 1) * (HID * NB);
        float*       hnext = g_h + (size_t)((t + 1) & 1) * (HID * NB);
        const float* hp = hprev + (size_t)(wid * 128) * 64;  // this warp's k-rows

        // x-part preacts (independent of h; issued early)
        float4 xp = *(const float4*)&g_xproj[((size_t)t * 64 + m) * NC + C0 + jl * 4];

        ull acc[16];
#pragma unroll
        for (int i = 0; i < 16; i++) acc[i] = 0;

        PFW(stW, 0);
        PFW(stW + 512, 8);

        for (int sub = 0; sub < 16; sub++) {
            if (sub == 15) { CP_WAIT0(); } else { CP_WAIT1(); }
            __syncwarp();
            const float* cur = stW + ((sub & 1) << 9);
            const float* wp  = Wsm + (wid * 128 + sub * 8) * 16 + ci * 4;
#pragma unroll
            for (int kk = 0; kk < 8; kk++) {
                ulonglong2 a0 = *(const ulonglong2*)(cur + kk * 64 + mi * 8);
                ulonglong2 a1 = *(const ulonglong2*)(cur + kk * 64 + mi * 8 + 4);
                float4 bv = *(const float4*)(wp + kk * 16);
                ull d0 = dup2(bv.x), d1 = dup2(bv.y), d2 = dup2(bv.z), d3 = dup2(bv.w);
                fma2(acc[0],  a0.x, d0); fma2(acc[1],  a0.x, d1);
                fma2(acc[2],  a0.x, d2); fma2(acc[3],  a0.x, d3);
                fma2(acc[4],  a0.y, d0); fma2(acc[5],  a0.y, d1);
                fma2(acc[6],  a0.y, d2); fma2(acc[7],  a0.y, d3);
                fma2(acc[8],  a1.x, d0); fma2(acc[9],  a1.x, d1);
                fma2(acc[10], a1.x, d2); fma2(acc[11], a1.x, d3);
                fma2(acc[12], a1.y, d0); fma2(acc[13], a1.y, d1);
                fma2(acc[14], a1.y, d2); fma2(acc[15], a1.y, d3);
            }
            if (sub < 14) { PFW(stW + ((sub & 1) << 9), (sub + 2) * 8); }
        }

        // ---- split-K partials -> smem (alias stages: 8 x 32P x 16c ull = 32 KB) ----
        __syncthreads();
        ull* R = (ull*)stg;
        {
            int base = wid * 512;
#pragma unroll
            for (int p = 0; p < 4; p++) {
                int Pp = mi * 4 + p;
#pragma unroll
                for (int cc = 0; cc < 4; cc++) {
                    int c = ci * 4 + cc;
                    R[base + Pp * 16 + swz(c, Pp)] = acc[p * 4 + cc];
                }
            }
        }
        __syncthreads();

        // ---- gates: thread -> (m, j); direct 8-slice reduction ----
        float pre[4];
#pragma unroll
        for (int g = 0; g < 4; g++) {
            int c = jl * 4 + g;
            int o = P * 16 + swz(c, P);
            ull s = add2(add2(add2(R[o], R[512 + o]),
                              add2(R[1024 + o], R[1536 + o])),
                         add2(add2(R[2048 + o], R[2560 + o]),
                              add2(R[3072 + o], R[3584 + o])));
            float lo, hi; up2(s, lo, hi);
            pre[g] = e ? hi : lo;
        }
        pre[0] += xp.x; pre[1] += xp.y; pre[2] += xp.z; pre[3] += xp.w;

        float is = 1.f / (1.f + __expf(-pre[0]));
        float fs = 1.f / (1.f + __expf(-pre[1]));
        float gt = tanhf(pre[2]);
        float os = 1.f / (1.f + __expf(-pre[3]));

        float cn = fs * c_reg + is * gt;
        c_reg = cn;
        float hv = os * tanhf(cn);
        hnext[(size_t)j * 64 + m] = hv;                   // coalesced (m across lanes)
        out[((size_t)t * 64 + m) * 1024 + j] = hv;

        // ---- software grid barrier (all 256 CTAs resident: 2 CTAs/SM) ----
        __threadfence();
        __syncthreads();
        if (tid == 0) {
            atomicAdd((unsigned*)&g_bar, 1u);
            unsigned target = (unsigned)(t + 1) * NCTAS;
            while (g_bar < target) { }
        }
        __syncthreads();
        __threadfence();
    }
#undef PFW
}

// ---------------- launcher ----------------
extern "C" void kernel_launch(void* const* d_in, const int* in_sizes, int n_in,
                              void* d_out, int out_size)
{
    const int*   x   = (const int*)  d_in[0];
    const float* emb = (const float*)d_in[1];
    const float* Wi  = (const float*)d_in[2];
    const float* bi  = (const float*)d_in[3];
    const float* Wf  = (const float*)d_in[4];
    const float* bf  = (const float*)d_in[5];
    const float* Wc  = (const float*)d_in[6];
    const float* bc  = (const float*)d_in[7];
    const float* Wo  = (const float*)d_in[8];
    const float* bo  = (const float*)d_in[9];
    float* out = (float*)d_out;
    (void)in_sizes; (void)n_in; (void)out_size;

    static bool attr_done = false;
    if (!attr_done) {
        cudaFuncSetAttribute(k_lstm, cudaFuncAttributeMaxDynamicSharedMemorySize,
                             SMEM_LSTM);
        attr_done = true;
    }

    k_init<<<(HID * NB + 255) / 256, 256>>>();
    k_reorg<<<((HID + EMB) * HID + 255) / 256, 256>>>(Wi, bi, Wf, bf, Wc, bc, Wo, bo);

    dim3 g1(16, 512);
    k_embed_proj<<<g1, 256>>>(x, emb);

    k_lstm<<<NCTAS, 256, SMEM_LSTM>>>(out);
}